// round 9
// baseline (speedup 1.0000x reference)
#include <cuda_runtime.h>
#include <math_constants.h>

// Problem constants
#define B_ 32
#define L_ 8192
#define C_ 256
#define S_ 32                 // L-splits
#define CHUNK_ (L_ / S_)      // 256
#define MLP_ 8

// Partials, padded row-major: part4[row][s*2 + {0,1}], row = b*C + c.
// Slot layout: {mn0,mn1,mn2,mx0} {mx1,mx2,pad,pad}. 8192 rows * 1KB = 8MB.
__device__ float4 g_part4[(size_t)B_ * C_ * S_ * 2];
// Completion counters, one per batch. Zero-init; reset by reducer each run.
__device__ int g_cnt[B_];

// Merge running ascending triple with ascending (a0,a1,a2): keep 3 smallest. 7 ops.
__device__ __forceinline__ void merge_min(float a0, float a1, float a2,
                                          float& mn0, float& mn1, float& mn2) {
    float x0 = fminf(mn0, a0);
    float y0 = fmaxf(mn0, a0);
    float x1 = fminf(mn1, a1);
    float x2 = fminf(mn2, a2);
    float t  = fmaxf(x1, y0);
    mn0 = x0;
    mn1 = fminf(y0, x1);
    mn2 = fminf(x2, t);
}

// Merge running descending triple with descending (d0,d1,d2): keep 3 largest. 7 ops.
__device__ __forceinline__ void merge_max(float d0, float d1, float d2,
                                          float& mx0, float& mx1, float& mx2) {
    float x0 = fmaxf(mx0, d0);
    float y0 = fminf(mx0, d0);
    float x1 = fmaxf(mx1, d1);
    float x2 = fmaxf(mx2, d2);
    float t  = fminf(x1, y0);
    mx0 = x0;
    mx1 = fmaxf(y0, x1);
    mx2 = fmaxf(x2, t);
}

// Sort quad (10 ops) then merge both sides (7+7): 24 ops / 4 elements.
__device__ __forceinline__ void quad_update(float v0, float v1, float v2, float v3,
                                            float& mn0, float& mn1, float& mn2,
                                            float& mx0, float& mx1, float& mx2) {
    float a = fminf(v0, v1), b = fmaxf(v0, v1);
    float c = fminf(v2, v3), d = fmaxf(v2, v3);
    float a0 = fminf(a, c), t0 = fmaxf(a, c);
    float t1 = fminf(b, d), a3 = fmaxf(b, d);
    float a1 = fminf(t0, t1), a2 = fmaxf(t0, t1);
    merge_min(a0, a1, a2, mn0, mn1, mn2);   // a3 provably not among 3 smallest
    merge_max(a3, a2, a1, mx0, mx1, mx2);   // a0 provably not among 3 largest
}

// Single fused kernel: grid (S, B) = 1024 blocks x 256 threads, one full
// resident wave at 8 blocks/SM (64 warps/SM). Each block scans its chunk
// branchlessly and stores partials; the LAST block to finish for batch b
// reduces all 256 rows of that batch and writes the final output.
__global__ __launch_bounds__(C_, 8) void kmm_fused(const float* __restrict__ x,
                                                   float* __restrict__ out) {
    const int c = threadIdx.x;
    const int s = blockIdx.x;
    const int b = blockIdx.y;

    const float* __restrict__ p =
        x + ((size_t)b * L_ + (size_t)s * CHUNK_) * C_ + c;

    float mx0 = -CUDART_INF_F, mx1 = -CUDART_INF_F, mx2 = -CUDART_INF_F;
    float mn0 =  CUDART_INF_F, mn1 =  CUDART_INF_F, mn2 =  CUDART_INF_F;

    for (int l = 0; l < CHUNK_; l += MLP_) {
        float v[MLP_];
#pragma unroll
        for (int j = 0; j < MLP_; j++)
            v[j] = __ldg(p + (size_t)(l + j) * C_);
        quad_update(v[0], v[1], v[2], v[3], mn0, mn1, mn2, mx0, mx1, mx2);
        quad_update(v[4], v[5], v[6], v[7], mn0, mn1, mn2, mx0, mx1, mx2);
    }

    float4* o4 = g_part4 + ((size_t)(b * C_ + c) * S_ + s) * 2;
    o4[0] = make_float4(mn0, mn1, mn2, mx0);
    o4[1] = make_float4(mx1, mx2, 0.f, 0.f);

    // ---- last-block reduction for this batch ----
    __shared__ int amLast;
    __threadfence();
    if (threadIdx.x == 0) {
        int old = atomicAdd(&g_cnt[b], 1);
        amLast = (old == S_ - 1);
    }
    __syncthreads();
    if (!amLast) return;

    // Reducer: 8 warps; per iteration a warp handles 2 rows.
    // lane = r*16 + s0 (r in {0,1}, s0 in 0..15); lane loads slots s0, s0+16
    // of its row (coalesced: warp touches 2 rows x 1KB). Local merge, then
    // 4 butterfly rounds within the 16-lane group.
    const int wid  = threadIdx.x >> 5;
    const int lane = threadIdx.x & 31;
    const int r    = lane >> 4;          // row within pair
    const int s0   = lane & 15;          // slot index (first of two)

    for (int iter = 0; iter < 16; iter++) {
        const int row = b * C_ + wid * 32 + iter * 2 + r;
        const float4* base = g_part4 + (size_t)row * S_ * 2;

        float4 a0 = __ldcg(base + s0 * 2);
        float4 b0 = __ldcg(base + s0 * 2 + 1);
        float4 a1 = __ldcg(base + (s0 + 16) * 2);
        float4 b1 = __ldcg(base + (s0 + 16) * 2 + 1);

        float n0 = a0.x, n1 = a0.y, n2 = a0.z;
        float m0 = a0.w, m1 = b0.x, m2 = b0.y;
        merge_min(a1.x, a1.y, a1.z, n0, n1, n2);
        merge_max(a1.w, b1.x, b1.y, m0, m1, m2);

#pragma unroll
        for (int off = 8; off > 0; off >>= 1) {
            float q0 = __shfl_xor_sync(0xffffffffu, n0, off);
            float q1 = __shfl_xor_sync(0xffffffffu, n1, off);
            float q2 = __shfl_xor_sync(0xffffffffu, n2, off);
            float w0 = __shfl_xor_sync(0xffffffffu, m0, off);
            float w1 = __shfl_xor_sync(0xffffffffu, m1, off);
            float w2 = __shfl_xor_sync(0xffffffffu, m2, off);
            merge_min(q0, q1, q2, n0, n1, n2);
            merge_max(w0, w1, w2, m0, m1, m2);
        }

        if (s0 == 0) {
            float* o = out + (size_t)row * 6;
            o[0] = n0; o[1] = n1; o[2] = n2;
            o[3] = m0; o[4] = m1; o[5] = m2;
        }
    }

    // Reset counter so graph replays start clean.
    if (threadIdx.x == 0) g_cnt[b] = 0;
}

extern "C" void kernel_launch(void* const* d_in, const int* in_sizes, int n_in,
                              void* d_out, int out_size) {
    const float* x = (const float*)d_in[0];
    float* out = (float*)d_out;

    dim3 grid(S_, B_);
    kmm_fused<<<grid, C_>>>(x, out);
}

// round 10
// speedup vs baseline: 1.3694x; 1.3694x over previous
#include <cuda_runtime.h>
#include <math_constants.h>

// Problem constants
#define B_ 32
#define L_ 8192
#define C_ 256
#define S_ 32                 // L-splits
#define CHUNK_ (L_ / S_)      // 256
#define MLP_ 4

// Partials, padded row-major: part4[row][s*2 + {0,1}], row = b*C + c.
// Slot layout: {mn0,mn1,mn2,mx0} {mx1,mx2,pad,pad}. 8192 rows * 1KB = 8MB.
__device__ float4 g_part4[(size_t)B_ * C_ * S_ * 2];

// Merge running ascending triple with ascending (a0,a1,a2): keep 3 smallest. 7 ops.
__device__ __forceinline__ void merge_min(float a0, float a1, float a2,
                                          float& mn0, float& mn1, float& mn2) {
    float x0 = fminf(mn0, a0);
    float y0 = fmaxf(mn0, a0);
    float x1 = fminf(mn1, a1);
    float x2 = fminf(mn2, a2);
    float t  = fmaxf(x1, y0);
    mn0 = x0;
    mn1 = fminf(y0, x1);
    mn2 = fminf(x2, t);
}

// Merge running descending triple with descending (d0,d1,d2): keep 3 largest. 7 ops.
__device__ __forceinline__ void merge_max(float d0, float d1, float d2,
                                          float& mx0, float& mx1, float& mx2) {
    float x0 = fmaxf(mx0, d0);
    float y0 = fminf(mx0, d0);
    float x1 = fmaxf(mx1, d1);
    float x2 = fmaxf(mx2, d2);
    float t  = fminf(x1, y0);
    mx0 = x0;
    mx1 = fmaxf(y0, x1);
    mx2 = fmaxf(x2, t);
}

// Sort quad (10 ops) then merge both sides (7+7): 24 ops / 4 elements.
__device__ __forceinline__ void quad_update(float v0, float v1, float v2, float v3,
                                            float& mn0, float& mn1, float& mn2,
                                            float& mx0, float& mx1, float& mx2) {
    float a = fminf(v0, v1), b = fmaxf(v0, v1);
    float c = fminf(v2, v3), d = fmaxf(v2, v3);
    float a0 = fminf(a, c), t0 = fmaxf(a, c);
    float t1 = fminf(b, d), a3 = fmaxf(b, d);
    float a1 = fminf(t0, t1), a2 = fmaxf(t0, t1);
    merge_min(a0, a1, a2, mn0, mn1, mn2);   // a3 provably not among 3 smallest
    merge_max(a3, a2, a1, mx0, mx1, mx2);   // a0 provably not among 3 largest
}

// Pass 1: grid (S, B) = 1024 blocks x 256 threads = one full resident wave
// at 8 blocks/SM (64 warps/SM). Thread c scans CHUNK_ l-values, branchless.
// MLP=4 front-batched streaming loads: still covers DRAM latency (32KB/SM in
// flight vs ~14KB needed) while cutting cross-CTA L1tex-queue spread.
// __ldcs = evict-first so the input stream doesn't evict partials from L2.
__global__ __launch_bounds__(C_, 8) void kmm_partial(const float* __restrict__ x) {
    const int c = threadIdx.x;
    const int s = blockIdx.x;
    const int b = blockIdx.y;

    const float* __restrict__ p =
        x + ((size_t)b * L_ + (size_t)s * CHUNK_) * C_ + c;

    float mx0 = -CUDART_INF_F, mx1 = -CUDART_INF_F, mx2 = -CUDART_INF_F;
    float mn0 =  CUDART_INF_F, mn1 =  CUDART_INF_F, mn2 =  CUDART_INF_F;

    for (int l = 0; l < CHUNK_; l += MLP_) {
        float v[MLP_];
#pragma unroll
        for (int j = 0; j < MLP_; j++)
            v[j] = __ldcs(p + (size_t)(l + j) * C_);
        quad_update(v[0], v[1], v[2], v[3], mn0, mn1, mn2, mx0, mx1, mx2);
    }

    float4* o4 = g_part4 + ((size_t)(b * C_ + c) * S_ + s) * 2;
    o4[0] = make_float4(mn0, mn1, mn2, mx0);
    o4[1] = make_float4(mx1, mx2, 0.f, 0.f);
}

// Pass 2: warp covers 4 rows; lane = rowgrp*8 + s0, loads slots
// s0, s0+8, s0+16, s0+24 (8 independent LDG.128 in flight), merges them
// locally, then 3 butterfly rounds within its 8-lane group.
__global__ __launch_bounds__(256) void kmm_reduce(float* __restrict__ out) {
    const int gtid = blockIdx.x * 256 + threadIdx.x;
    const int lane = gtid & 31;
    const int s0   = lane & 7;
    const int row  = (gtid >> 5) * 4 + (lane >> 3);

    const float4* base = g_part4 + (size_t)row * S_ * 2;

    float4 a[4], bq[4];
#pragma unroll
    for (int k = 0; k < 4; k++) {
        a[k]  = __ldg(base + (s0 + k * 8) * 2);
        bq[k] = __ldg(base + (s0 + k * 8) * 2 + 1);
    }

    float mn0 = a[0].x, mn1 = a[0].y, mn2 = a[0].z;
    float mx0 = a[0].w, mx1 = bq[0].x, mx2 = bq[0].y;
#pragma unroll
    for (int k = 1; k < 4; k++) {
        merge_min(a[k].x, a[k].y, a[k].z, mn0, mn1, mn2);
        merge_max(a[k].w, bq[k].x, bq[k].y, mx0, mx1, mx2);
    }

#pragma unroll
    for (int off = 4; off > 0; off >>= 1) {
        float b0 = __shfl_xor_sync(0xffffffffu, mn0, off);
        float b1 = __shfl_xor_sync(0xffffffffu, mn1, off);
        float b2 = __shfl_xor_sync(0xffffffffu, mn2, off);
        float c0 = __shfl_xor_sync(0xffffffffu, mx0, off);
        float c1 = __shfl_xor_sync(0xffffffffu, mx1, off);
        float c2 = __shfl_xor_sync(0xffffffffu, mx2, off);
        merge_min(b0, b1, b2, mn0, mn1, mn2);
        merge_max(c0, c1, c2, mx0, mx1, mx2);
    }

    if (s0 == 0) {
        float* r = out + (size_t)row * 6;
        r[0] = mn0; r[1] = mn1; r[2] = mn2;
        r[3] = mx0; r[4] = mx1; r[5] = mx2;
    }
}

extern "C" void kernel_launch(void* const* d_in, const int* in_sizes, int n_in,
                              void* d_out, int out_size) {
    const float* x = (const float*)d_in[0];
    float* out = (float*)d_out;

    dim3 grid1(S_, B_);
    kmm_partial<<<grid1, C_>>>(x);

    // 8192 rows / 4 rows-per-warp = 2048 warps = 256 blocks x 256 threads
    kmm_reduce<<<256, 256>>>(out);
}